// round 1
// baseline (speedup 1.0000x reference)
#include <cuda_runtime.h>
#include <cuda_bf16.h>
#include <cstdint>

// Problem constants
#define NB   128          // batch
#define NT   64           // max timesteps
#define NE   512          // embedding dim
#define NH   1024         // hidden dim
#define N3H  3072         // 3*H (gate order r,z,n)
#define NBT  (NB*NT)      // 8192 rows for xgates GEMM

// Scratch (device globals; no runtime allocation allowed)
__device__ float g_xg[(size_t)NT * NB * N3H];   // [t][b][3H]  ~100 MB
__device__ float g_h[2][NB * NH];               // ping-pong hidden state
__device__ float g_final[NB * NH];              // h at t == len-1

// ---------------------------------------------------------------------------
// helpers
// ---------------------------------------------------------------------------
__device__ __forceinline__ uint32_t f2tf32(float x) {
    uint32_t r;
    asm("cvt.rna.tf32.f32 %0, %1;" : "=r"(r) : "f"(x));
    return r;
}

__device__ __forceinline__ void mma_tf32(float c[4], const uint32_t a[4],
                                         uint32_t b0, uint32_t b1) {
    asm volatile(
        "mma.sync.aligned.m16n8k8.row.col.f32.tf32.tf32.f32 "
        "{%0,%1,%2,%3}, {%4,%5,%6,%7}, {%8,%9}, {%0,%1,%2,%3};"
        : "+f"(c[0]), "+f"(c[1]), "+f"(c[2]), "+f"(c[3])
        : "r"(a[0]), "r"(a[1]), "r"(a[2]), "r"(a[3]), "r"(b0), "r"(b1));
}

// ---------------------------------------------------------------------------
// k_init: zero h[0]
// ---------------------------------------------------------------------------
__global__ void k_init() {
    int i = blockIdx.x * blockDim.x + threadIdx.x;
    if (i < NB * NH) g_h[0][i] = 0.0f;
}

// ---------------------------------------------------------------------------
// k_xgates: xg[t][b][n] = sum_k emb_table[sent[b,t]][k] * w_ih[n][k] + b_ih[n]
// GEMM: M=8192 (m = b*64 + t), N=3072, K=512.  Tile 128x128, KC=32.
// 256 threads = 8 warps as 4(m) x 2(n); warp tile 32x64.
// ---------------------------------------------------------------------------
__global__ void __launch_bounds__(256, 2)
k_xgates(const int* __restrict__ sent, const float* __restrict__ emb,
         const float* __restrict__ w_ih, const float* __restrict__ b_ih) {
    __shared__ uint32_t sA[128][36];
    __shared__ uint32_t sB[128][36];

    const int tid  = threadIdx.x;
    const int wid  = tid >> 5;
    const int lane = tid & 31;
    const int g    = lane >> 2;
    const int t4   = lane & 3;

    const int m0 = blockIdx.y * 128;
    const int n0 = blockIdx.x * 128;
    const int wm = (wid & 3) * 32;   // warp m offset within tile
    const int wn = (wid >> 2) * 64;  // warp n offset within tile

    float c[2][8][4];
#pragma unroll
    for (int mf = 0; mf < 2; mf++)
#pragma unroll
        for (int nt = 0; nt < 8; nt++)
#pragma unroll
            for (int e = 0; e < 4; e++) c[mf][nt][e] = 0.0f;

    for (int kk = 0; kk < NE; kk += 32) {
        __syncthreads();
        // fill A: 128 rows x 32 cols, gathered embedding rows (tf32)
#pragma unroll
        for (int p = 0; p < 4; p++) {
            int idx = tid + p * 256;
            int row = idx >> 3;
            int col = (idx & 7) << 2;
            int tok = sent[m0 + row];
            const float4 v = *reinterpret_cast<const float4*>(
                emb + (size_t)tok * NE + kk + col);
            uint4 u = make_uint4(f2tf32(v.x), f2tf32(v.y), f2tf32(v.z), f2tf32(v.w));
            *reinterpret_cast<uint4*>(&sA[row][col]) = u;
        }
        // fill B: w_ih rows n0..n0+127
#pragma unroll
        for (int p = 0; p < 4; p++) {
            int idx = tid + p * 256;
            int row = idx >> 3;
            int col = (idx & 7) << 2;
            const float4 v = *reinterpret_cast<const float4*>(
                w_ih + (size_t)(n0 + row) * NE + kk + col);
            uint4 u = make_uint4(f2tf32(v.x), f2tf32(v.y), f2tf32(v.z), f2tf32(v.w));
            *reinterpret_cast<uint4*>(&sB[row][col]) = u;
        }
        __syncthreads();

#pragma unroll
        for (int k8 = 0; k8 < 32; k8 += 8) {
            uint32_t a[2][4];
#pragma unroll
            for (int mf = 0; mf < 2; mf++) {
                int r = wm + mf * 16 + g;
                a[mf][0] = sA[r][k8 + t4];
                a[mf][1] = sA[r + 8][k8 + t4];
                a[mf][2] = sA[r][k8 + t4 + 4];
                a[mf][3] = sA[r + 8][k8 + t4 + 4];
            }
#pragma unroll
            for (int nt = 0; nt < 8; nt++) {
                uint32_t b0 = sB[wn + nt * 8 + g][k8 + t4];
                uint32_t b1 = sB[wn + nt * 8 + g][k8 + t4 + 4];
                mma_tf32(c[0][nt], a[0], b0, b1);
                mma_tf32(c[1][nt], a[1], b0, b1);
            }
        }
    }

    // epilogue: add b_ih, scatter to g_xg[t][b][n]
#pragma unroll
    for (int mf = 0; mf < 2; mf++) {
#pragma unroll
        for (int nt = 0; nt < 8; nt++) {
#pragma unroll
            for (int half = 0; half < 2; half++) {  // row g vs g+8
                int m = m0 + wm + mf * 16 + g + half * 8;
                int b = m >> 6;
                int tt = m & 63;
                int n = n0 + wn + nt * 8 + (t4 << 1);
                float2 out;
                out.x = c[mf][nt][half * 2 + 0] + b_ih[n];
                out.y = c[mf][nt][half * 2 + 1] + b_ih[n + 1];
                *reinterpret_cast<float2*>(
                    &g_xg[((size_t)tt * NB + b) * N3H + n]) = out;
            }
        }
    }
}

// ---------------------------------------------------------------------------
// k_step: one GRU timestep.
// 128 CTAs, each owns 8 hidden units (j0 = blockIdx.x*8).
// Computes hr,hz,hn (K=1024) with tf32 mma, fuses gate math, writes h_new,
// captures h at t == len-1.
// ---------------------------------------------------------------------------
__global__ void __launch_bounds__(256)
k_step(int t, int pp, const int* __restrict__ slen,
       const float* __restrict__ w_hh, const float* __restrict__ b_hh) {
    __shared__ uint32_t sH[128][36];
    __shared__ uint32_t sW[24][36];

    const float* __restrict__ h_in = g_h[pp];
    float* __restrict__ h_out = g_h[pp ^ 1];

    const int tid  = threadIdx.x;
    const int wid  = tid >> 5;
    const int lane = tid & 31;
    const int g    = lane >> 2;
    const int t4   = lane & 3;
    const int j0   = blockIdx.x * 8;

    float c[3][4];
#pragma unroll
    for (int nt = 0; nt < 3; nt++)
#pragma unroll
        for (int e = 0; e < 4; e++) c[nt][e] = 0.0f;

    for (int kk = 0; kk < NH; kk += 32) {
        __syncthreads();
        // fill sH: 128 rows (batch) x 32 cols of h_in (tf32)
#pragma unroll
        for (int p = 0; p < 4; p++) {
            int idx = tid + p * 256;
            int row = idx >> 3;
            int col = (idx & 7) << 2;
            const float4 v = *reinterpret_cast<const float4*>(
                h_in + (size_t)row * NH + kk + col);
            uint4 u = make_uint4(f2tf32(v.x), f2tf32(v.y), f2tf32(v.z), f2tf32(v.w));
            *reinterpret_cast<uint4*>(&sH[row][col]) = u;
        }
        // fill sW: 24 rows = {r,z,n} x 8 units
        if (tid < 192) {
            int r   = tid >> 3;           // 0..23
            int col = (tid & 7) << 2;     // 0..28
            int grow = (r >> 3) * NH + j0 + (r & 7);  // global w_hh row
            const float4 v = *reinterpret_cast<const float4*>(
                w_hh + (size_t)grow * NH + kk + col);
            uint4 u = make_uint4(f2tf32(v.x), f2tf32(v.y), f2tf32(v.z), f2tf32(v.w));
            *reinterpret_cast<uint4*>(&sW[r][col]) = u;
        }
        __syncthreads();

#pragma unroll
        for (int k8 = 0; k8 < 32; k8 += 8) {
            uint32_t a[4];
            int r = wid * 16 + g;
            a[0] = sH[r][k8 + t4];
            a[1] = sH[r + 8][k8 + t4];
            a[2] = sH[r][k8 + t4 + 4];
            a[3] = sH[r + 8][k8 + t4 + 4];
#pragma unroll
            for (int nt = 0; nt < 3; nt++) {
                uint32_t b0 = sW[nt * 8 + g][k8 + t4];
                uint32_t b1 = sW[nt * 8 + g][k8 + t4 + 4];
                mma_tf32(c[nt], a, b0, b1);
            }
        }
    }

    // fused GRU gate epilogue: thread owns (rows g, g+8) x (units 2*t4, 2*t4+1)
#pragma unroll
    for (int e = 0; e < 4; e++) {
        int row = wid * 16 + g + ((e >> 1) << 3);     // batch index
        int j   = j0 + (t4 << 1) + (e & 1);           // hidden unit
        float hr = c[0][e] + b_hh[j];
        float hz = c[1][e] + b_hh[NH + j];
        float hn = c[2][e] + b_hh[2 * NH + j];
        const float* xg = g_xg + ((size_t)t * NB + row) * N3H;
        float xr = xg[j];
        float xz = xg[NH + j];
        float xn = xg[2 * NH + j];
        float rr = 1.0f / (1.0f + expf(-(xr + hr)));
        float zz = 1.0f / (1.0f + expf(-(xz + hz)));
        float nn = tanhf(xn + rr * hn);
        float hold = h_in[(size_t)row * NH + j];
        float hnew = (1.0f - zz) * nn + zz * hold;
        h_out[(size_t)row * NH + j] = hnew;
        if (slen[row] - 1 == t) g_final[(size_t)row * NH + j] = hnew;
    }
}

// ---------------------------------------------------------------------------
// k_norm: L2-normalize each final row, write output
// ---------------------------------------------------------------------------
__global__ void __launch_bounds__(256)
k_norm(float* __restrict__ out) {
    const int b = blockIdx.x;
    const int tid = threadIdx.x;
    float s = 0.0f;
    for (int j = tid; j < NH; j += 256) {
        float v = g_final[(size_t)b * NH + j];
        s += v * v;
    }
#pragma unroll
    for (int o = 16; o; o >>= 1) s += __shfl_xor_sync(0xFFFFFFFFu, s, o);
    __shared__ float ws[8];
    __shared__ float s_norm;
    if ((tid & 31) == 0) ws[tid >> 5] = s;
    __syncthreads();
    if (tid == 0) {
        float x = 0.0f;
#pragma unroll
        for (int i = 0; i < 8; i++) x += ws[i];
        s_norm = sqrtf(x);
    }
    __syncthreads();
    float inv = 1.0f / s_norm;
    for (int j = tid; j < NH; j += 256)
        out[(size_t)b * NH + j] = g_final[(size_t)b * NH + j] * inv;
}

// ---------------------------------------------------------------------------
// entry point
// ---------------------------------------------------------------------------
extern "C" void kernel_launch(void* const* d_in, const int* in_sizes, int n_in,
                              void* d_out, int out_size) {
    const int*   sent  = (const int*)d_in[0];
    const int*   slen  = (const int*)d_in[1];
    const float* emb   = (const float*)d_in[2];
    const float* w_ih  = (const float*)d_in[3];
    const float* w_hh  = (const float*)d_in[4];
    const float* b_ih  = (const float*)d_in[5];
    const float* b_hh  = (const float*)d_in[6];

    k_init<<<512, 256>>>();
    k_xgates<<<dim3(N3H / 128, NBT / 128), 256>>>(sent, emb, w_ih, b_ih);
    for (int t = 0; t < NT; t++) {
        k_step<<<128, 256>>>(t, t & 1, slen, w_hh, b_hh);
    }
    k_norm<<<NB, 256>>>((float*)d_out);
}

// round 2
// speedup vs baseline: 1.6889x; 1.6889x over previous
#include <cuda_runtime.h>
#include <cuda_bf16.h>
#include <cstdint>

// Problem constants
#define NB   128          // batch
#define NT   64           // max timesteps
#define NE   512          // embedding dim
#define NH   1024         // hidden dim
#define N3H  3072         // 3*H (gate order r,z,n)
#define NBT  (NB*NT)      // 8192 rows for xgates GEMM

#define SW_STRIDE 1028    // 1024 + 4 pad (conflict-free fragment reads)
#define SH_STRIDE 36      // 32 + 4 pad, 144B rows (16B aligned)

// Scratch (device globals; no runtime allocation allowed)
__device__ float g_xg[(size_t)NT * NB * N3H];   // [t][b][3H]
__device__ float g_h[2][NB * NH];               // ping-pong hidden state
__device__ float g_final[NB * NH];              // h at t == len-1
__device__ unsigned g_bar;                      // grid barrier counter

// ---------------------------------------------------------------------------
// helpers
// ---------------------------------------------------------------------------
__device__ __forceinline__ uint32_t f2tf32(float x) {
    uint32_t r;
    asm("cvt.rna.tf32.f32 %0, %1;" : "=r"(r) : "f"(x));
    return r;
}

__device__ __forceinline__ void mma_tf32(float c[4], const uint32_t a[4],
                                         uint32_t b0, uint32_t b1) {
    asm volatile(
        "mma.sync.aligned.m16n8k8.row.col.f32.tf32.tf32.f32 "
        "{%0,%1,%2,%3}, {%4,%5,%6,%7}, {%8,%9}, {%0,%1,%2,%3};"
        : "+f"(c[0]), "+f"(c[1]), "+f"(c[2]), "+f"(c[3])
        : "r"(a[0]), "r"(a[1]), "r"(a[2]), "r"(a[3]), "r"(b0), "r"(b1));
}

__device__ __forceinline__ void cp_async16(uint32_t saddr, const void* gaddr) {
    asm volatile("cp.async.cg.shared.global [%0], [%1], 16;"
                 :: "r"(saddr), "l"(gaddr));
}
__device__ __forceinline__ void cp_commit() {
    asm volatile("cp.async.commit_group;");
}
template <int N>
__device__ __forceinline__ void cp_wait() {
    asm volatile("cp.async.wait_group %0;" :: "n"(N));
}

// ---------------------------------------------------------------------------
// k_init: zero h[0] and the grid barrier counter
// ---------------------------------------------------------------------------
__global__ void k_init() {
    int i = blockIdx.x * blockDim.x + threadIdx.x;
    if (i < NB * NH) g_h[0][i] = 0.0f;
    if (i == 0) g_bar = 0u;
}

// ---------------------------------------------------------------------------
// k_xgates: xg[t][b][n] = emb_table[sent[b,t]] . w_ih[n] + b_ih[n]
// GEMM M=8192, N=3072, K=512. Tile 128x128, KC=32. (unchanged from R0)
// ---------------------------------------------------------------------------
__global__ void __launch_bounds__(256, 2)
k_xgates(const int* __restrict__ sent, const float* __restrict__ emb,
         const float* __restrict__ w_ih, const float* __restrict__ b_ih) {
    __shared__ uint32_t sA[128][36];
    __shared__ uint32_t sB[128][36];

    const int tid  = threadIdx.x;
    const int wid  = tid >> 5;
    const int lane = tid & 31;
    const int g    = lane >> 2;
    const int t4   = lane & 3;

    const int m0 = blockIdx.y * 128;
    const int n0 = blockIdx.x * 128;
    const int wm = (wid & 3) * 32;
    const int wn = (wid >> 2) * 64;

    float c[2][8][4];
#pragma unroll
    for (int mf = 0; mf < 2; mf++)
#pragma unroll
        for (int nt = 0; nt < 8; nt++)
#pragma unroll
            for (int e = 0; e < 4; e++) c[mf][nt][e] = 0.0f;

    for (int kk = 0; kk < NE; kk += 32) {
        __syncthreads();
#pragma unroll
        for (int p = 0; p < 4; p++) {
            int idx = tid + p * 256;
            int row = idx >> 3;
            int col = (idx & 7) << 2;
            int tok = sent[m0 + row];
            const float4 v = *reinterpret_cast<const float4*>(
                emb + (size_t)tok * NE + kk + col);
            uint4 u = make_uint4(f2tf32(v.x), f2tf32(v.y), f2tf32(v.z), f2tf32(v.w));
            *reinterpret_cast<uint4*>(&sA[row][col]) = u;
        }
#pragma unroll
        for (int p = 0; p < 4; p++) {
            int idx = tid + p * 256;
            int row = idx >> 3;
            int col = (idx & 7) << 2;
            const float4 v = *reinterpret_cast<const float4*>(
                w_ih + (size_t)(n0 + row) * NE + kk + col);
            uint4 u = make_uint4(f2tf32(v.x), f2tf32(v.y), f2tf32(v.z), f2tf32(v.w));
            *reinterpret_cast<uint4*>(&sB[row][col]) = u;
        }
        __syncthreads();

#pragma unroll
        for (int k8 = 0; k8 < 32; k8 += 8) {
            uint32_t a[2][4];
#pragma unroll
            for (int mf = 0; mf < 2; mf++) {
                int r = wm + mf * 16 + g;
                a[mf][0] = sA[r][k8 + t4];
                a[mf][1] = sA[r + 8][k8 + t4];
                a[mf][2] = sA[r][k8 + t4 + 4];
                a[mf][3] = sA[r + 8][k8 + t4 + 4];
            }
#pragma unroll
            for (int nt = 0; nt < 8; nt++) {
                uint32_t b0 = sB[wn + nt * 8 + g][k8 + t4];
                uint32_t b1 = sB[wn + nt * 8 + g][k8 + t4 + 4];
                mma_tf32(c[0][nt], a[0], b0, b1);
                mma_tf32(c[1][nt], a[1], b0, b1);
            }
        }
    }

#pragma unroll
    for (int mf = 0; mf < 2; mf++) {
#pragma unroll
        for (int nt = 0; nt < 8; nt++) {
#pragma unroll
            for (int half = 0; half < 2; half++) {
                int m = m0 + wm + mf * 16 + g + half * 8;
                int b = m >> 6;
                int tt = m & 63;
                int n = n0 + wn + nt * 8 + (t4 << 1);
                float2 out;
                out.x = c[mf][nt][half * 2 + 0] + b_ih[n];
                out.y = c[mf][nt][half * 2 + 1] + b_ih[n + 1];
                *reinterpret_cast<float2*>(
                    &g_xg[((size_t)tt * NB + b) * N3H + n]) = out;
            }
        }
    }
}

// ---------------------------------------------------------------------------
// k_recur: PERSISTENT GRU recurrence. 128 CTAs x 256 threads, all co-resident.
// Each CTA owns 8 hidden units; w_hh rows (24 x 1024, tf32) live in smem for
// all 64 timesteps. h tiles stream via cp.async.cg double-buffering. Steps
// separated by a global counter barrier.
// Dynamic smem: sW 24*1028 words + sH 2*128*36 words = 135552 bytes.
// ---------------------------------------------------------------------------
__global__ void __launch_bounds__(256)
k_recur(const int* __restrict__ slen, const float* __restrict__ w_hh,
        const float* __restrict__ b_hh) {
    extern __shared__ uint32_t sm[];
    uint32_t* sW = sm;                        // [24][SW_STRIDE]
    uint32_t* sH = sm + 24 * SW_STRIDE;       // [2][128][SH_STRIDE]

    const int tid  = threadIdx.x;
    const int wid  = tid >> 5;
    const int lane = tid & 31;
    const int g    = lane >> 2;
    const int t4   = lane & 3;
    const int j0   = blockIdx.x * 8;
    const unsigned nb = gridDim.x;

    // ---- load this CTA's 24 w_hh rows into smem as tf32 (once) ----
    for (int i = tid; i < 24 * 256; i += 256) {     // 256 float4 per row
        int r  = i >> 8;
        int c4 = (i & 255) << 2;
        int grow = (r >> 3) * NH + j0 + (r & 7);
        const float4 v = *reinterpret_cast<const float4*>(
            w_hh + (size_t)grow * NH + c4);
        uint32_t* d = sW + r * SW_STRIDE + c4;
        d[0] = f2tf32(v.x); d[1] = f2tf32(v.y);
        d[2] = f2tf32(v.z); d[3] = f2tf32(v.w);
    }

    // ---- per-thread constants for the epilogue ----
    const int r0 = wid * 16 + g;     // batch rows r0, r0+8
    const int r1 = r0 + 8;
    const int ja = j0 + (t4 << 1);   // hidden units ja, ja+1
    const int jb = ja + 1;
    const int len0 = slen[r0] - 1;
    const int len1 = slen[r1] - 1;
    const float bra = b_hh[ja],          brb = b_hh[jb];
    const float bza = b_hh[NH + ja],     bzb = b_hh[NH + jb];
    const float bna = b_hh[2 * NH + ja], bnb = b_hh[2 * NH + jb];

    __syncthreads();   // sW ready

    for (int t = 0; t < NT; t++) {
        const float* __restrict__ h_in = g_h[t & 1];
        float* __restrict__ h_out = g_h[(t & 1) ^ 1];

        float c[3][4];
#pragma unroll
        for (int nt = 0; nt < 3; nt++)
#pragma unroll
            for (int e = 0; e < 4; e++) c[nt][e] = 0.0f;

        // prologue: stage 0 <- tile 0
        {
            const int row = tid >> 3;
            const int col = (tid & 7) << 2;
#pragma unroll
            for (int p = 0; p < 4; p++) {
                int rr = row + p * 32;
                uint32_t sa = (uint32_t)__cvta_generic_to_shared(
                    sH + rr * SH_STRIDE + col);
                cp_async16(sa, h_in + (size_t)rr * NH + col);
            }
            cp_commit();
        }

        for (int it = 0; it < 32; it++) {
            const int cur = it & 1;
            __syncthreads();   // everyone done reading stage cur^1
            if (it + 1 < 32) {
                const int kk = (it + 1) * 32;
                const int row = tid >> 3;
                const int col = (tid & 7) << 2;
                uint32_t* dst = sH + (cur ^ 1) * 128 * SH_STRIDE;
#pragma unroll
                for (int p = 0; p < 4; p++) {
                    int rr = row + p * 32;
                    uint32_t sa = (uint32_t)__cvta_generic_to_shared(
                        dst + rr * SH_STRIDE + col);
                    cp_async16(sa, h_in + (size_t)rr * NH + kk + col);
                }
                cp_commit();
                cp_wait<1>();
            } else {
                cp_wait<0>();
            }
            __syncthreads();   // stage cur globally visible

            const uint32_t* S = sH + cur * 128 * SH_STRIDE;
            const int kbase = it * 32;
#pragma unroll
            for (int k8 = 0; k8 < 32; k8 += 8) {
                uint32_t a[4];
                a[0] = S[r0 * SH_STRIDE + k8 + t4];
                a[1] = S[r1 * SH_STRIDE + k8 + t4];
                a[2] = S[r0 * SH_STRIDE + k8 + t4 + 4];
                a[3] = S[r1 * SH_STRIDE + k8 + t4 + 4];
#pragma unroll
                for (int nt = 0; nt < 3; nt++) {
                    const uint32_t* W = sW + (nt * 8 + g) * SW_STRIDE + kbase + k8 + t4;
                    mma_tf32(c[nt], a, W[0], W[4]);
                }
            }
        }

        // ---- fused GRU gate epilogue ----
        {
            const float* xg0 = g_xg + ((size_t)t * NB + r0) * N3H;
            const float* xg1 = g_xg + ((size_t)t * NB + r1) * N3H;
#pragma unroll
            for (int e = 0; e < 4; e++) {
                const int  row = (e >> 1) ? r1 : r0;
                const int  j   = (e & 1) ? jb : ja;
                const float* xg = (e >> 1) ? xg1 : xg0;
                const float bhr = (e & 1) ? brb : bra;
                const float bhz = (e & 1) ? bzb : bza;
                const float bhn = (e & 1) ? bnb : bna;
                float hr = c[0][e] + bhr;
                float hz = c[1][e] + bhz;
                float hn = c[2][e] + bhn;
                float xr = xg[j];
                float xz = xg[NH + j];
                float xn = xg[2 * NH + j];
                float rr = 1.0f / (1.0f + expf(-(xr + hr)));
                float zz = 1.0f / (1.0f + expf(-(xz + hz)));
                float nn = tanhf(xn + rr * hn);
                float hold = __ldcg(h_in + (size_t)row * NH + j);
                float hnew = (1.0f - zz) * nn + zz * hold;
                h_out[(size_t)row * NH + j] = hnew;
                const int lt = (e >> 1) ? len1 : len0;
                if (lt == t) g_final[(size_t)row * NH + j] = hnew;
            }
        }

        // ---- grid barrier ----
        __syncthreads();
        if (tid == 0) {
            __threadfence();
            atomicAdd(&g_bar, 1u);
            const unsigned target = (unsigned)(t + 1) * nb;
            while (*(volatile unsigned*)&g_bar < target) { }
            __threadfence();
        }
        __syncthreads();
    }
}

// ---------------------------------------------------------------------------
// k_norm: L2-normalize each final row, write output
// ---------------------------------------------------------------------------
__global__ void __launch_bounds__(256)
k_norm(float* __restrict__ out) {
    const int b = blockIdx.x;
    const int tid = threadIdx.x;
    float s = 0.0f;
    for (int j = tid; j < NH; j += 256) {
        float v = g_final[(size_t)b * NH + j];
        s += v * v;
    }
#pragma unroll
    for (int o = 16; o; o >>= 1) s += __shfl_xor_sync(0xFFFFFFFFu, s, o);
    __shared__ float ws[8];
    __shared__ float s_norm;
    if ((tid & 31) == 0) ws[tid >> 5] = s;
    __syncthreads();
    if (tid == 0) {
        float x = 0.0f;
#pragma unroll
        for (int i = 0; i < 8; i++) x += ws[i];
        s_norm = sqrtf(x);
    }
    __syncthreads();
    float inv = 1.0f / s_norm;
    for (int j = tid; j < NH; j += 256)
        out[(size_t)b * NH + j] = g_final[(size_t)b * NH + j] * inv;
}

// ---------------------------------------------------------------------------
// entry point
// ---------------------------------------------------------------------------
extern "C" void kernel_launch(void* const* d_in, const int* in_sizes, int n_in,
                              void* d_out, int out_size) {
    const int*   sent  = (const int*)d_in[0];
    const int*   slen  = (const int*)d_in[1];
    const float* emb   = (const float*)d_in[2];
    const float* w_ih  = (const float*)d_in[3];
    const float* w_hh  = (const float*)d_in[4];
    const float* b_ih  = (const float*)d_in[5];
    const float* b_hh  = (const float*)d_in[6];

    const int smem_recur = (24 * SW_STRIDE + 2 * 128 * SH_STRIDE) * 4;  // 135552
    cudaFuncSetAttribute(k_recur, cudaFuncAttributeMaxDynamicSharedMemorySize,
                         smem_recur);

    k_init<<<512, 256>>>();
    k_xgates<<<dim3(N3H / 128, NBT / 128), 256>>>(sent, emb, w_ih, b_ih);
    k_recur<<<128, 256, smem_recur>>>(slen, w_hh, b_hh);
    k_norm<<<NB, 256>>>((float*)d_out);
}

// round 3
// speedup vs baseline: 3.0545x; 1.8086x over previous
#include <cuda_runtime.h>
#include <cuda_fp16.h>
#include <cuda_bf16.h>
#include <cstdint>

// Problem constants
#define NB   128          // batch
#define NT   64           // max timesteps
#define NE   512          // embedding dim
#define NH   1024         // hidden dim
#define N3H  3072         // 3*H (gate order r,z,n)
#define NBT  (NB*NT)      // 8192 rows for xgates GEMM

// k_recur smem geometry (32-bit words)
#define SWW   516         // w_hh row stride: 512 words (1024 fp16) + 4 pad
#define SHW   36          // h stage row stride: 32 words (64 fp16) + 4 pad
#define NSTG  5           // cp.async ring depth
#define STGW  (128*SHW)   // words per stage

// Scratch (device globals; no runtime allocation allowed)
__device__ float g_xg[(size_t)NT * NB * N3H];              // [t][b][3H]
__device__ float g_h[2][NB * NH];                          // fp32 state ping-pong
__device__ __align__(16) __half g_h16[2][NB * NH];         // fp16 broadcast copy
__device__ float g_final[NB * NH];                         // h at t == len-1
__device__ unsigned g_bar;                                 // grid barrier counter

// ---------------------------------------------------------------------------
// helpers
// ---------------------------------------------------------------------------
__device__ __forceinline__ uint32_t f2tf32(float x) {
    uint32_t r;
    asm("cvt.rna.tf32.f32 %0, %1;" : "=r"(r) : "f"(x));
    return r;
}

__device__ __forceinline__ void mma_tf32(float c[4], const uint32_t a[4],
                                         uint32_t b0, uint32_t b1) {
    asm volatile(
        "mma.sync.aligned.m16n8k8.row.col.f32.tf32.tf32.f32 "
        "{%0,%1,%2,%3}, {%4,%5,%6,%7}, {%8,%9}, {%0,%1,%2,%3};"
        : "+f"(c[0]), "+f"(c[1]), "+f"(c[2]), "+f"(c[3])
        : "r"(a[0]), "r"(a[1]), "r"(a[2]), "r"(a[3]), "r"(b0), "r"(b1));
}

__device__ __forceinline__ void mma_f16(float c[4], const uint32_t a[4],
                                        uint32_t b0, uint32_t b1) {
    asm volatile(
        "mma.sync.aligned.m16n8k16.row.col.f32.f16.f16.f32 "
        "{%0,%1,%2,%3}, {%4,%5,%6,%7}, {%8,%9}, {%0,%1,%2,%3};"
        : "+f"(c[0]), "+f"(c[1]), "+f"(c[2]), "+f"(c[3])
        : "r"(a[0]), "r"(a[1]), "r"(a[2]), "r"(a[3]), "r"(b0), "r"(b1));
}

__device__ __forceinline__ void cp_async16(uint32_t saddr, const void* gaddr) {
    asm volatile("cp.async.cg.shared.global [%0], [%1], 16;"
                 :: "r"(saddr), "l"(gaddr));
}
__device__ __forceinline__ void cp_commit() {
    asm volatile("cp.async.commit_group;");
}
template <int N>
__device__ __forceinline__ void cp_wait() {
    asm volatile("cp.async.wait_group %0;" :: "n"(N));
}

// ---------------------------------------------------------------------------
// k_init: zero h0 (fp32 + fp16) and the grid barrier counter
// ---------------------------------------------------------------------------
__global__ void k_init() {
    int i = blockIdx.x * blockDim.x + threadIdx.x;
    if (i < NB * NH) {
        g_h[0][i] = 0.0f;
        g_h16[0][i] = __float2half(0.0f);
    }
    if (i == 0) g_bar = 0u;
}

// ---------------------------------------------------------------------------
// k_xgates: xg[t][b][n] = emb_table[sent[b,t]] . w_ih[n] + b_ih[n]
// GEMM M=8192, N=3072, K=512. Tile 128x128, KC=32. tf32. (unchanged)
// ---------------------------------------------------------------------------
__global__ void __launch_bounds__(256, 2)
k_xgates(const int* __restrict__ sent, const float* __restrict__ emb,
         const float* __restrict__ w_ih, const float* __restrict__ b_ih) {
    __shared__ uint32_t sA[128][36];
    __shared__ uint32_t sB[128][36];

    const int tid  = threadIdx.x;
    const int wid  = tid >> 5;
    const int lane = tid & 31;
    const int g    = lane >> 2;
    const int t4   = lane & 3;

    const int m0 = blockIdx.y * 128;
    const int n0 = blockIdx.x * 128;
    const int wm = (wid & 3) * 32;
    const int wn = (wid >> 2) * 64;

    float c[2][8][4];
#pragma unroll
    for (int mf = 0; mf < 2; mf++)
#pragma unroll
        for (int nt = 0; nt < 8; nt++)
#pragma unroll
            for (int e = 0; e < 4; e++) c[mf][nt][e] = 0.0f;

    for (int kk = 0; kk < NE; kk += 32) {
        __syncthreads();
#pragma unroll
        for (int p = 0; p < 4; p++) {
            int idx = tid + p * 256;
            int row = idx >> 3;
            int col = (idx & 7) << 2;
            int tok = sent[m0 + row];
            const float4 v = *reinterpret_cast<const float4*>(
                emb + (size_t)tok * NE + kk + col);
            uint4 u = make_uint4(f2tf32(v.x), f2tf32(v.y), f2tf32(v.z), f2tf32(v.w));
            *reinterpret_cast<uint4*>(&sA[row][col]) = u;
        }
#pragma unroll
        for (int p = 0; p < 4; p++) {
            int idx = tid + p * 256;
            int row = idx >> 3;
            int col = (idx & 7) << 2;
            const float4 v = *reinterpret_cast<const float4*>(
                w_ih + (size_t)(n0 + row) * NE + kk + col);
            uint4 u = make_uint4(f2tf32(v.x), f2tf32(v.y), f2tf32(v.z), f2tf32(v.w));
            *reinterpret_cast<uint4*>(&sB[row][col]) = u;
        }
        __syncthreads();

#pragma unroll
        for (int k8 = 0; k8 < 32; k8 += 8) {
            uint32_t a[2][4];
#pragma unroll
            for (int mf = 0; mf < 2; mf++) {
                int r = wm + mf * 16 + g;
                a[mf][0] = sA[r][k8 + t4];
                a[mf][1] = sA[r + 8][k8 + t4];
                a[mf][2] = sA[r][k8 + t4 + 4];
                a[mf][3] = sA[r + 8][k8 + t4 + 4];
            }
#pragma unroll
            for (int nt = 0; nt < 8; nt++) {
                uint32_t b0 = sB[wn + nt * 8 + g][k8 + t4];
                uint32_t b1 = sB[wn + nt * 8 + g][k8 + t4 + 4];
                mma_tf32(c[0][nt], a[0], b0, b1);
                mma_tf32(c[1][nt], a[1], b0, b1);
            }
        }
    }

#pragma unroll
    for (int mf = 0; mf < 2; mf++) {
#pragma unroll
        for (int nt = 0; nt < 8; nt++) {
#pragma unroll
            for (int half = 0; half < 2; half++) {
                int m = m0 + wm + mf * 16 + g + half * 8;
                int b = m >> 6;
                int tt = m & 63;
                int n = n0 + wn + nt * 8 + (t4 << 1);
                float2 out;
                out.x = c[mf][nt][half * 2 + 0] + b_ih[n];
                out.y = c[mf][nt][half * 2 + 1] + b_ih[n + 1];
                *reinterpret_cast<float2*>(
                    &g_xg[((size_t)tt * NB + b) * N3H + n]) = out;
            }
        }
    }
}

// ---------------------------------------------------------------------------
// k_recur: PERSISTENT GRU recurrence, fp16 MMA.
// 128 CTAs x 256 threads. Each CTA owns 8 hidden units; w_hh rows (24 x 1024)
// live in smem as fp16 for all 64 steps. h broadcast streams as fp16 through a
// 5-stage cp.async ring (64 halves per stage). fp32 h state kept separately.
// smem = 24*SWW + NSTG*STGW words = 141,696 bytes.
// ---------------------------------------------------------------------------
__global__ void __launch_bounds__(256)
k_recur(const int* __restrict__ slen, const float* __restrict__ w_hh,
        const float* __restrict__ b_hh) {
    extern __shared__ uint32_t sm[];
    uint32_t* sW = sm;                 // [24][SWW] (each word = 2 fp16)
    uint32_t* sH = sm + 24 * SWW;      // [NSTG][128][SHW]

    const int tid  = threadIdx.x;
    const int wid  = tid >> 5;
    const int lane = tid & 31;
    const int g    = lane >> 2;
    const int t4   = lane & 3;
    const int j0   = blockIdx.x * 8;
    const unsigned nb = gridDim.x;

    // ---- convert this CTA's 24 w_hh rows to fp16 in smem (once) ----
    for (int i = tid; i < 24 * 256; i += 256) {       // 256 float4 per row
        int r  = i >> 8;
        int c4 = (i & 255) << 2;                      // float index
        int grow = (r >> 3) * NH + j0 + (r & 7);
        const float4 v = *reinterpret_cast<const float4*>(
            w_hh + (size_t)grow * NH + c4);
        __half2 p0 = __floats2half2_rn(v.x, v.y);
        __half2 p1 = __floats2half2_rn(v.z, v.w);
        uint32_t* d = sW + r * SWW + (c4 >> 1);
        d[0] = *reinterpret_cast<uint32_t*>(&p0);
        d[1] = *reinterpret_cast<uint32_t*>(&p1);
    }

    // ---- per-thread constants ----
    const int r0 = wid * 16 + g;       // batch rows r0, r0+8
    const int r1 = r0 + 8;
    const int ja = j0 + (t4 << 1);     // hidden units ja, ja+1
    const int len0 = slen[r0] - 1;
    const int len1 = slen[r1] - 1;
    const float bra = b_hh[ja],          brb = b_hh[ja + 1];
    const float bza = b_hh[NH + ja],     bzb = b_hh[NH + ja + 1];
    const float bna = b_hh[2 * NH + ja], bnb = b_hh[2 * NH + ja + 1];

    // cp.async source coordinates for this thread
    const int ldrow = tid >> 3;        // +p*32
    const int ldcol = tid & 7;         // 16B chunk within 128B

    __syncthreads();   // sW ready

    for (int t = 0; t < NT; t++) {
        const __half* __restrict__ h16_in = g_h16[t & 1];
        const float*  __restrict__ h_in   = g_h[t & 1];
        float*  __restrict__ h_out   = g_h[(t & 1) ^ 1];
        __half* __restrict__ h16_out = g_h16[(t & 1) ^ 1];

        // ---- prefetch epilogue operands (hides scattered DRAM reads) ----
        const float* xg0 = g_xg + ((size_t)t * NB + r0) * N3H + ja;
        const float* xg1 = g_xg + ((size_t)t * NB + r1) * N3H + ja;
        float2 xr0 = __ldg((const float2*)(xg0));
        float2 xz0 = __ldg((const float2*)(xg0 + NH));
        float2 xn0 = __ldg((const float2*)(xg0 + 2 * NH));
        float2 xr1 = __ldg((const float2*)(xg1));
        float2 xz1 = __ldg((const float2*)(xg1 + NH));
        float2 xn1 = __ldg((const float2*)(xg1 + 2 * NH));
        float2 hold0 = *(const float2*)(h_in + (size_t)r0 * NH + ja);
        float2 hold1 = *(const float2*)(h_in + (size_t)r1 * NH + ja);

        float c[3][4];
#pragma unroll
        for (int nt = 0; nt < 3; nt++)
#pragma unroll
            for (int e = 0; e < 4; e++) c[nt][e] = 0.0f;

        // ---- prologue: fill stages 0..3 ----
#pragma unroll
        for (int s = 0; s < NSTG - 1; s++) {
            uint32_t* dst = sH + s * STGW;
#pragma unroll
            for (int p = 0; p < 4; p++) {
                int rr = ldrow + p * 32;
                uint32_t sa = (uint32_t)__cvta_generic_to_shared(
                    dst + rr * SHW + (ldcol << 2));
                cp_async16(sa, h16_in + (size_t)rr * NH + s * 64 + (ldcol << 3));
            }
            cp_commit();
        }

        // ---- 16 stages of 64 halves each ----
        for (int it = 0; it < 16; it++) {
            cp_wait<NSTG - 2>();       // group `it` (stage it%5) complete
            __syncthreads();           // visible to all; prior compute done

            const int nxt = it + NSTG - 1;
            if (nxt < 16) {
                uint32_t* dst = sH + (nxt % NSTG) * STGW;
#pragma unroll
                for (int p = 0; p < 4; p++) {
                    int rr = ldrow + p * 32;
                    uint32_t sa = (uint32_t)__cvta_generic_to_shared(
                        dst + rr * SHW + (ldcol << 2));
                    cp_async16(sa, h16_in + (size_t)rr * NH + nxt * 64 + (ldcol << 3));
                }
            }
            cp_commit();               // empty group in tail keeps FIFO aligned

            const uint32_t* S = sH + (it % NSTG) * STGW;
            const int kw = it * 32;    // word offset into sW rows
#pragma unroll
            for (int kb = 0; kb < 32; kb += 8) {
                uint32_t a[4];
                a[0] = S[r0 * SHW + kb + t4];
                a[1] = S[r1 * SHW + kb + t4];
                a[2] = S[r0 * SHW + kb + t4 + 4];
                a[3] = S[r1 * SHW + kb + t4 + 4];
#pragma unroll
                for (int nt = 0; nt < 3; nt++) {
                    const uint32_t* W = sW + (nt * 8 + g) * SWW + kw + kb + t4;
                    mma_f16(c[nt], a, W[0], W[4]);
                }
            }
        }

        // ---- fused GRU gate epilogue ----
        {
            float hnew[4];
#pragma unroll
            for (int e = 0; e < 4; e++) {
                const int half = e >> 1;     // 0: r0, 1: r1
                const int sub  = e & 1;      // 0: ja, 1: ja+1
                float xr = half ? (sub ? xr1.y : xr1.x) : (sub ? xr0.y : xr0.x);
                float xz = half ? (sub ? xz1.y : xz1.x) : (sub ? xz0.y : xz0.x);
                float xn = half ? (sub ? xn1.y : xn1.x) : (sub ? xn0.y : xn0.x);
                float ho = half ? (sub ? hold1.y : hold1.x) : (sub ? hold0.y : hold0.x);
                float hr = c[0][e] + (sub ? brb : bra);
                float hz = c[1][e] + (sub ? bzb : bza);
                float hn = c[2][e] + (sub ? bnb : bna);
                float rr = 1.0f / (1.0f + expf(-(xr + hr)));
                float zz = 1.0f / (1.0f + expf(-(xz + hz)));
                float nn = tanhf(xn + rr * hn);
                hnew[e] = (1.0f - zz) * nn + zz * ho;
            }
            *(float2*)(h_out + (size_t)r0 * NH + ja) = make_float2(hnew[0], hnew[1]);
            *(float2*)(h_out + (size_t)r1 * NH + ja) = make_float2(hnew[2], hnew[3]);
            __half2 p0 = __floats2half2_rn(hnew[0], hnew[1]);
            __half2 p1 = __floats2half2_rn(hnew[2], hnew[3]);
            *(__half2*)(h16_out + (size_t)r0 * NH + ja) = p0;
            *(__half2*)(h16_out + (size_t)r1 * NH + ja) = p1;
            if (len0 == t)
                *(float2*)(g_final + (size_t)r0 * NH + ja) = make_float2(hnew[0], hnew[1]);
            if (len1 == t)
                *(float2*)(g_final + (size_t)r1 * NH + ja) = make_float2(hnew[2], hnew[3]);
        }

        // ---- grid barrier ----
        __syncthreads();
        if (tid == 0) {
            __threadfence();
            atomicAdd(&g_bar, 1u);
            const unsigned target = (unsigned)(t + 1) * nb;
            while (*(volatile unsigned*)&g_bar < target) { }
            __threadfence();
        }
        __syncthreads();
    }
}

// ---------------------------------------------------------------------------
// k_norm: L2-normalize each final row, write output
// ---------------------------------------------------------------------------
__global__ void __launch_bounds__(256)
k_norm(float* __restrict__ out) {
    const int b = blockIdx.x;
    const int tid = threadIdx.x;
    float s = 0.0f;
    for (int j = tid; j < NH; j += 256) {
        float v = g_final[(size_t)b * NH + j];
        s += v * v;
    }
#pragma unroll
    for (int o = 16; o; o >>= 1) s += __shfl_xor_sync(0xFFFFFFFFu, s, o);
    __shared__ float ws[8];
    __shared__ float s_norm;
    if ((tid & 31) == 0) ws[tid >> 5] = s;
    __syncthreads();
    if (tid == 0) {
        float x = 0.0f;
#pragma unroll
        for (int i = 0; i < 8; i++) x += ws[i];
        s_norm = sqrtf(x);
    }
    __syncthreads();
    float inv = 1.0f / s_norm;
    for (int j = tid; j < NH; j += 256)
        out[(size_t)b * NH + j] = g_final[(size_t)b * NH + j] * inv;
}

// ---------------------------------------------------------------------------
// entry point
// ---------------------------------------------------------------------------
extern "C" void kernel_launch(void* const* d_in, const int* in_sizes, int n_in,
                              void* d_out, int out_size) {
    const int*   sent  = (const int*)d_in[0];
    const int*   slen  = (const int*)d_in[1];
    const float* emb   = (const float*)d_in[2];
    const float* w_ih  = (const float*)d_in[3];
    const float* w_hh  = (const float*)d_in[4];
    const float* b_ih  = (const float*)d_in[5];
    const float* b_hh  = (const float*)d_in[6];

    const int smem_recur = (24 * SWW + NSTG * STGW) * 4;   // 141,696 B
    cudaFuncSetAttribute(k_recur, cudaFuncAttributeMaxDynamicSharedMemorySize,
                         smem_recur);

    k_init<<<512, 256>>>();
    k_xgates<<<dim3(N3H / 128, NBT / 128), 256>>>(sent, emb, w_ih, b_ih);
    k_recur<<<128, 256, smem_recur>>>(slen, w_hh, b_hh);
    k_norm<<<NB, 256>>>((float*)d_out);
}

// round 4
// speedup vs baseline: 3.3779x; 1.1059x over previous
#include <cuda_runtime.h>
#include <cuda_fp16.h>
#include <cuda_bf16.h>
#include <cstdint>

// Problem constants
#define NB   128          // batch
#define NT   64           // max timesteps
#define NE   512          // embedding dim
#define NH   1024         // hidden dim
#define N3H  3072         // 3*H (gate order r,z,n)
#define NBT  (NB*NT)      // 8192 rows for xgates GEMM

// k_recur geometry: each CTA owns 32 units x 32 batch rows
#define UCNT   32                 // hidden units per CTA
#define BROWS  32                 // batch rows per CTA
#define SWROWS 96                 // 3 gates * 32 units
#define SWW    516                // w_hh row stride (512 words = 1024 fp16) + 4 pad
#define SHW    36                 // h stage row stride: 32 words (64 fp16) + 4 pad
#define NSTG   6                  // cp.async ring depth
#define STGW   (BROWS * SHW)      // words per stage (1152)

// Scratch (device globals; no runtime allocation allowed)
__device__ float g_xg[(size_t)NT * NB * N3H];              // [t][b][3H]
__device__ float g_h[2][NB * NH];                          // fp32 state ping-pong
__device__ __align__(16) __half g_h16[2][NB * NH];         // fp16 broadcast copy
__device__ float g_final[NB * NH];                         // h at t == len-1
__device__ unsigned g_bar;                                 // barrier arrival counter
__device__ unsigned g_epoch;                               // barrier release epoch

// ---------------------------------------------------------------------------
// helpers
// ---------------------------------------------------------------------------
__device__ __forceinline__ void mma_tf32(float c[4], const uint32_t a[4],
                                         uint32_t b0, uint32_t b1) {
    asm volatile(
        "mma.sync.aligned.m16n8k8.row.col.f32.tf32.tf32.f32 "
        "{%0,%1,%2,%3}, {%4,%5,%6,%7}, {%8,%9}, {%0,%1,%2,%3};"
        : "+f"(c[0]), "+f"(c[1]), "+f"(c[2]), "+f"(c[3])
        : "r"(a[0]), "r"(a[1]), "r"(a[2]), "r"(a[3]), "r"(b0), "r"(b1));
}

__device__ __forceinline__ void mma_f16(float c[4], const uint32_t a[4],
                                        uint32_t b0, uint32_t b1) {
    asm volatile(
        "mma.sync.aligned.m16n8k16.row.col.f32.f16.f16.f32 "
        "{%0,%1,%2,%3}, {%4,%5,%6,%7}, {%8,%9}, {%0,%1,%2,%3};"
        : "+f"(c[0]), "+f"(c[1]), "+f"(c[2]), "+f"(c[3])
        : "r"(a[0]), "r"(a[1]), "r"(a[2]), "r"(a[3]), "r"(b0), "r"(b1));
}

__device__ __forceinline__ void cp_async16(uint32_t saddr, const void* gaddr) {
    asm volatile("cp.async.cg.shared.global [%0], [%1], 16;"
                 :: "r"(saddr), "l"(gaddr));
}
__device__ __forceinline__ void cp_commit() {
    asm volatile("cp.async.commit_group;");
}
template <int N>
__device__ __forceinline__ void cp_wait() {
    asm volatile("cp.async.wait_group %0;" :: "n"(N));
}

// ---------------------------------------------------------------------------
// k_init: zero h0 (fp32 + fp16) and the barrier words
// ---------------------------------------------------------------------------
__global__ void k_init() {
    int i = blockIdx.x * blockDim.x + threadIdx.x;
    if (i < NB * NH) {
        g_h[0][i] = 0.0f;
        g_h16[0][i] = __float2half(0.0f);
    }
    if (i == 0) { g_bar = 0u; g_epoch = 0u; }
}

// ---------------------------------------------------------------------------
// k_xgates: xg[t][b][n] = emb_table[sent[b,t]] . w_ih[n] + b_ih[n]
// GEMM M=8192, N=3072, K=512. Tile 128x128, KC=32.
// cp.async double-buffered fp32 tiles; raw fp32 bits fed as tf32 (truncation).
// Dynamic smem: 2 stages x (A 128x36 + B 128x36) words = 73,728 B.
// ---------------------------------------------------------------------------
__global__ void __launch_bounds__(256, 2)
k_xgates(const int* __restrict__ sent, const float* __restrict__ emb,
         const float* __restrict__ w_ih, const float* __restrict__ b_ih) {
    extern __shared__ uint32_t xsm[];
    // layout: sA[2][128][36], sB[2][128][36]
    uint32_t* sA = xsm;
    uint32_t* sB = xsm + 2 * 128 * 36;

    const int tid  = threadIdx.x;
    const int wid  = tid >> 5;
    const int lane = tid & 31;
    const int g    = lane >> 2;
    const int t4   = lane & 3;

    const int m0 = blockIdx.y * 128;
    const int n0 = blockIdx.x * 128;
    const int wm = (wid & 3) * 32;
    const int wn = (wid >> 2) * 64;

    // per-thread load coordinates (4 chunks of 16B)
    int ldrow[4], ldcol[4], ldtok[4];
#pragma unroll
    for (int p = 0; p < 4; p++) {
        int idx = tid + p * 256;
        ldrow[p] = idx >> 3;
        ldcol[p] = (idx & 7) << 2;
        ldtok[p] = sent[m0 + ldrow[p]];
    }

    float c[2][8][4];
#pragma unroll
    for (int mf = 0; mf < 2; mf++)
#pragma unroll
        for (int nt = 0; nt < 8; nt++)
#pragma unroll
            for (int e = 0; e < 4; e++) c[mf][nt][e] = 0.0f;

    // prologue: stage 0 <- ktile 0
#pragma unroll
    for (int p = 0; p < 4; p++) {
        uint32_t sa = (uint32_t)__cvta_generic_to_shared(
            sA + ldrow[p] * 36 + ldcol[p]);
        cp_async16(sa, emb + (size_t)ldtok[p] * NE + ldcol[p]);
        uint32_t sb = (uint32_t)__cvta_generic_to_shared(
            sB + ldrow[p] * 36 + ldcol[p]);
        cp_async16(sb, w_ih + (size_t)(n0 + ldrow[p]) * NE + ldcol[p]);
    }
    cp_commit();

    for (int kt = 0; kt < 16; kt++) {
        const int cur = kt & 1;
        if (kt + 1 < 16) {
            const int nxt = cur ^ 1;
            const int kk = (kt + 1) * 32;
#pragma unroll
            for (int p = 0; p < 4; p++) {
                uint32_t sa = (uint32_t)__cvta_generic_to_shared(
                    sA + nxt * 128 * 36 + ldrow[p] * 36 + ldcol[p]);
                cp_async16(sa, emb + (size_t)ldtok[p] * NE + kk + ldcol[p]);
                uint32_t sb = (uint32_t)__cvta_generic_to_shared(
                    sB + nxt * 128 * 36 + ldrow[p] * 36 + ldcol[p]);
                cp_async16(sb, w_ih + (size_t)(n0 + ldrow[p]) * NE + kk + ldcol[p]);
            }
        }
        cp_commit();
        cp_wait<1>();          // stage kt complete
        __syncthreads();

        const uint32_t* A = sA + cur * 128 * 36;
        const uint32_t* B = sB + cur * 128 * 36;
#pragma unroll
        for (int k8 = 0; k8 < 32; k8 += 8) {
            uint32_t a[2][4];
#pragma unroll
            for (int mf = 0; mf < 2; mf++) {
                int r = wm + mf * 16 + g;
                a[mf][0] = A[r * 36 + k8 + t4];
                a[mf][1] = A[(r + 8) * 36 + k8 + t4];
                a[mf][2] = A[r * 36 + k8 + t4 + 4];
                a[mf][3] = A[(r + 8) * 36 + k8 + t4 + 4];
            }
#pragma unroll
            for (int nt = 0; nt < 8; nt++) {
                uint32_t b0 = B[(wn + nt * 8 + g) * 36 + k8 + t4];
                uint32_t b1 = B[(wn + nt * 8 + g) * 36 + k8 + t4 + 4];
                mma_tf32(c[0][nt], a[0], b0, b1);
                mma_tf32(c[1][nt], a[1], b0, b1);
            }
        }
        __syncthreads();       // done reading stage cur before it is refilled
    }

#pragma unroll
    for (int mf = 0; mf < 2; mf++) {
#pragma unroll
        for (int nt = 0; nt < 8; nt++) {
#pragma unroll
            for (int half = 0; half < 2; half++) {
                int m = m0 + wm + mf * 16 + g + half * 8;
                int b = m >> 6;
                int tt = m & 63;
                int n = n0 + wn + nt * 8 + (t4 << 1);
                float2 out;
                out.x = c[mf][nt][half * 2 + 0] + b_ih[n];
                out.y = c[mf][nt][half * 2 + 1] + b_ih[n + 1];
                *reinterpret_cast<float2*>(
                    &g_xg[((size_t)tt * NB + b) * N3H + n]) = out;
            }
        }
    }
}

// ---------------------------------------------------------------------------
// k_recur: PERSISTENT GRU recurrence, fp16 MMA.
// 128 CTAs = 32 unit-groups x 4 batch-quarters. Each CTA owns 32 units x
// 32 batch rows: w_hh rows (96 x 1024 fp16) in smem for all 64 steps; h
// broadcast reads only its 32 rows -> 8 MB/step chip-wide (4x less than R2).
// Barrier: atomicAdd arrivals + separate epoch word for polling.
// Dynamic smem = 96*516 + 6*1152 words = 225,792 B.
// ---------------------------------------------------------------------------
__global__ void __launch_bounds__(256)
k_recur(const int* __restrict__ slen, const float* __restrict__ w_hh,
        const float* __restrict__ b_hh) {
    extern __shared__ uint32_t sm[];
    uint32_t* sW = sm;                    // [96][SWW] (each word = 2 fp16)
    uint32_t* sH = sm + SWROWS * SWW;     // [NSTG][32][SHW]

    const int tid  = threadIdx.x;
    const int wid  = tid >> 5;
    const int lane = tid & 31;
    const int g    = lane >> 2;
    const int t4   = lane & 3;

    const int ug = blockIdx.x >> 2;       // unit group 0..31
    const int bq = blockIdx.x & 3;        // batch quarter 0..3
    const int j0 = ug * UCNT;
    const int b0 = bq * BROWS;

    // warp roles: bh = batch half (16 rows), uh = unit octet (8 units)
    const int bh = wid & 1;
    const int uh = wid >> 1;

    // ---- convert this CTA's 96 w_hh rows to fp16 in smem (once) ----
    for (int i = tid; i < SWROWS * 256; i += 256) {   // 256 float4 per row
        int r  = i >> 8;
        int c4 = (i & 255) << 2;                      // float index
        int grow = (r >> 5) * NH + j0 + (r & 31);
        const float4 v = *reinterpret_cast<const float4*>(
            w_hh + (size_t)grow * NH + c4);
        __half2 p0 = __floats2half2_rn(v.x, v.y);
        __half2 p1 = __floats2half2_rn(v.z, v.w);
        uint32_t* d = sW + r * SWW + (c4 >> 1);
        d[0] = *reinterpret_cast<uint32_t*>(&p0);
        d[1] = *reinterpret_cast<uint32_t*>(&p1);
    }

    // ---- per-thread constants ----
    const int r0c = bh * 16 + g;          // CTA-local rows r0c, r0c+8
    const int r0g = b0 + r0c;             // global batch rows
    const int r1g = r0g + 8;
    const int ja  = j0 + uh * 8 + (t4 << 1);   // hidden units ja, ja+1
    const int len0 = slen[r0g] - 1;
    const int len1 = slen[r1g] - 1;
    const float bra = b_hh[ja],          brb = b_hh[ja + 1];
    const float bza = b_hh[NH + ja],     bzb = b_hh[NH + ja + 1];
    const float bna = b_hh[2 * NH + ja], bnb = b_hh[2 * NH + ja + 1];

    // cp.async coordinates: one 16B chunk per thread per stage
    const int ldrow = tid >> 3;           // 0..31 (CTA-local row)
    const int ldcol = tid & 7;            // 16B chunk within 128B row-chunk

    __syncthreads();   // sW ready

    for (int t = 0; t < NT; t++) {
        const __half* __restrict__ h16_in = g_h16[t & 1];
        const float*  __restrict__ h_in   = g_h[t & 1];
        float*  __restrict__ h_out   = g_h[(t & 1) ^ 1];
        __half* __restrict__ h16_out = g_h16[(t & 1) ^ 1];

        // ---- prefetch epilogue operands ----
        const float* xg0 = g_xg + ((size_t)t * NB + r0g) * N3H + ja;
        const float* xg1 = g_xg + ((size_t)t * NB + r1g) * N3H + ja;
        float2 xr0 = __ldg((const float2*)(xg0));
        float2 xz0 = __ldg((const float2*)(xg0 + NH));
        float2 xn0 = __ldg((const float2*)(xg0 + 2 * NH));
        float2 xr1 = __ldg((const float2*)(xg1));
        float2 xz1 = __ldg((const float2*)(xg1 + NH));
        float2 xn1 = __ldg((const float2*)(xg1 + 2 * NH));
        float2 hold0 = *(const float2*)(h_in + (size_t)r0g * NH + ja);
        float2 hold1 = *(const float2*)(h_in + (size_t)r1g * NH + ja);

        float c[3][4];
#pragma unroll
        for (int nt = 0; nt < 3; nt++)
#pragma unroll
            for (int e = 0; e < 4; e++) c[nt][e] = 0.0f;

        // ---- prologue: fill stages 0..NSTG-2 ----
#pragma unroll
        for (int s = 0; s < NSTG - 1; s++) {
            uint32_t sa = (uint32_t)__cvta_generic_to_shared(
                sH + s * STGW + ldrow * SHW + (ldcol << 2));
            cp_async16(sa, h16_in + (size_t)(b0 + ldrow) * NH + s * 64 + (ldcol << 3));
            cp_commit();
        }

        // ---- 16 stages of 64 halves (k16 x4) each ----
        for (int it = 0; it < 16; it++) {
            cp_wait<NSTG - 2>();       // stage `it` complete
            __syncthreads();

            const int nxt = it + NSTG - 1;
            if (nxt < 16) {
                uint32_t sa = (uint32_t)__cvta_generic_to_shared(
                    sH + (nxt % NSTG) * STGW + ldrow * SHW + (ldcol << 2));
                cp_async16(sa, h16_in + (size_t)(b0 + ldrow) * NH + nxt * 64 + (ldcol << 3));
            }
            cp_commit();               // empty group in tail keeps FIFO aligned

            const uint32_t* S = sH + (it % NSTG) * STGW;
            const int kw = it * 32;    // word offset into sW rows
#pragma unroll
            for (int kb = 0; kb < 32; kb += 8) {
                uint32_t a[4];
                a[0] = S[r0c * SHW + kb + t4];
                a[1] = S[(r0c + 8) * SHW + kb + t4];
                a[2] = S[r0c * SHW + kb + t4 + 4];
                a[3] = S[(r0c + 8) * SHW + kb + t4 + 4];
#pragma unroll
                for (int nt = 0; nt < 3; nt++) {
                    const uint32_t* W = sW + (nt * UCNT + uh * 8 + g) * SWW + kw + kb + t4;
                    mma_f16(c[nt], a, W[0], W[4]);
                }
            }
        }

        // ---- fused GRU gate epilogue ----
        {
            float hnew[4];
#pragma unroll
            for (int e = 0; e < 4; e++) {
                const int half = e >> 1;
                const int sub  = e & 1;
                float xr = half ? (sub ? xr1.y : xr1.x) : (sub ? xr0.y : xr0.x);
                float xz = half ? (sub ? xz1.y : xz1.x) : (sub ? xz0.y : xz0.x);
                float xn = half ? (sub ? xn1.y : xn1.x) : (sub ? xn0.y : xn0.x);
                float ho = half ? (sub ? hold1.y : hold1.x) : (sub ? hold0.y : hold0.x);
                float hr = c[0][e] + (sub ? brb : bra);
                float hz = c[1][e] + (sub ? bzb : bza);
                float hn = c[2][e] + (sub ? bnb : bna);
                float rr = 1.0f / (1.0f + expf(-(xr + hr)));
                float zz = 1.0f / (1.0f + expf(-(xz + hz)));
                float nn = tanhf(xn + rr * hn);
                hnew[e] = (1.0f - zz) * nn + zz * ho;
            }
            *(float2*)(h_out + (size_t)r0g * NH + ja) = make_float2(hnew[0], hnew[1]);
            *(float2*)(h_out + (size_t)r1g * NH + ja) = make_float2(hnew[2], hnew[3]);
            __half2 p0 = __floats2half2_rn(hnew[0], hnew[1]);
            __half2 p1 = __floats2half2_rn(hnew[2], hnew[3]);
            *(__half2*)(h16_out + (size_t)r0g * NH + ja) = p0;
            *(__half2*)(h16_out + (size_t)r1g * NH + ja) = p1;
            if (len0 == t)
                *(float2*)(g_final + (size_t)r0g * NH + ja) = make_float2(hnew[0], hnew[1]);
            if (len1 == t)
                *(float2*)(g_final + (size_t)r1g * NH + ja) = make_float2(hnew[2], hnew[3]);
        }

        // ---- grid barrier: arrivals on g_bar, poll on g_epoch ----
        __syncthreads();
        if (tid == 0) {
            __threadfence();
            const unsigned target = (unsigned)(t + 1) * 128u;
            unsigned arr = atomicAdd(&g_bar, 1u) + 1u;
            if (arr == target) {
                *(volatile unsigned*)&g_epoch = (unsigned)(t + 1);
                __threadfence();
            } else {
                while (*(volatile unsigned*)&g_epoch < (unsigned)(t + 1)) { }
                __threadfence();
            }
        }
        __syncthreads();
    }
}

// ---------------------------------------------------------------------------
// k_norm: L2-normalize each final row, write output
// ---------------------------------------------------------------------------
__global__ void __launch_bounds__(256)
k_norm(float* __restrict__ out) {
    const int b = blockIdx.x;
    const int tid = threadIdx.x;
    float s = 0.0f;
    for (int j = tid; j < NH; j += 256) {
        float v = g_final[(size_t)b * NH + j];
        s += v * v;
    }
#pragma unroll
    for (int o = 16; o; o >>= 1) s += __shfl_xor_sync(0xFFFFFFFFu, s, o);
    __shared__ float ws[8];
    __shared__ float s_norm;
    if ((tid & 31) == 0) ws[tid >> 5] = s;
    __syncthreads();
    if (tid == 0) {
        float x = 0.0f;
#pragma unroll
        for (int i = 0; i < 8; i++) x += ws[i];
        s_norm = sqrtf(x);
    }
    __syncthreads();
    float inv = 1.0f / s_norm;
    for (int j = tid; j < NH; j += 256)
        out[(size_t)b * NH + j] = g_final[(size_t)b * NH + j] * inv;
}

// ---------------------------------------------------------------------------
// entry point
// ---------------------------------------------------------------------------
extern "C" void kernel_launch(void* const* d_in, const int* in_sizes, int n_in,
                              void* d_out, int out_size) {
    const int*   sent  = (const int*)d_in[0];
    const int*   slen  = (const int*)d_in[1];
    const float* emb   = (const float*)d_in[2];
    const float* w_ih  = (const float*)d_in[3];
    const float* w_hh  = (const float*)d_in[4];
    const float* b_ih  = (const float*)d_in[5];
    const float* b_hh  = (const float*)d_in[6];

    const int smem_xg    = 2 * 2 * 128 * 36 * 4;                    // 73,728 B
    const int smem_recur = (SWROWS * SWW + NSTG * STGW) * 4;        // 225,792 B
    cudaFuncSetAttribute(k_xgates, cudaFuncAttributeMaxDynamicSharedMemorySize,
                         smem_xg);
    cudaFuncSetAttribute(k_recur, cudaFuncAttributeMaxDynamicSharedMemorySize,
                         smem_recur);

    k_init<<<512, 256>>>();
    k_xgates<<<dim3(N3H / 128, NBT / 128), 256, smem_xg>>>(sent, emb, w_ih, b_ih);
    k_recur<<<128, 256, smem_recur>>>(slen, w_hh, b_hh);
    k_norm<<<NB, 256>>>((float*)d_out);
}